// round 1
// baseline (speedup 1.0000x reference)
#include <cuda_runtime.h>

typedef unsigned long long ull;

#define Dm     128
#define FFm    512
#define NROWSm 131072
#define NTILESm 1024   // NROWSm / 128
#define NPARTm 512
#define EPSm   1e-5f

// ---------------- device scratch (no cudaMalloc allowed) ----------------
__device__ float g_x[NROWSm * Dm];          // 64 MB running x
__device__ float g_part[NPARTm * Dm * Dm];  // 32 MB Gram partials
__device__ float g_G[Dm * Dm];
__device__ float g_T1[Dm * Dm];
__device__ float g_T2[Dm * Dm];
__device__ float g_M[Dm * Dm];

// ---------------- packed f32x2 helpers (Blackwell FFMA2) ----------------
__device__ __forceinline__ ull pk2(float lo, float hi) {
    ull r; asm("mov.b64 %0, {%1,%2};" : "=l"(r) : "f"(lo), "f"(hi)); return r;
}
__device__ __forceinline__ void upk2(ull v, float& lo, float& hi) {
    asm("mov.b64 {%0,%1}, %2;" : "=f"(lo), "=f"(hi) : "l"(v));
}
__device__ __forceinline__ void ffma2(ull& c, ull a, ull b) {
    asm("fma.rn.f32x2 %0, %1, %2, %3;" : "=l"(c) : "l"(a), "l"(b), "l"(c));
}

__device__ __forceinline__ float red16(float v) {
#pragma unroll
    for (int o = 8; o; o >>= 1) v += __shfl_xor_sync(0xffffffffu, v, o);
    return v;
}
__device__ __forceinline__ float red32(float v) {
#pragma unroll
    for (int o = 16; o; o >>= 1) v += __shfl_xor_sync(0xffffffffu, v, o);
    return v;
}

// acc2[i][p] += A[r0+i][k] * B[k][j0+2p .. 2p+1], k = 0..127
// A, B row-major [128][128] in shared memory.
__device__ __forceinline__ void mm88(const float* __restrict__ As,
                                     const float* __restrict__ Bs,
                                     int r0, int j0, ull (&acc2)[8][4]) {
#pragma unroll 4
    for (int k = 0; k < 128; ++k) {
        ulonglong2 b01 = *reinterpret_cast<const ulonglong2*>(Bs + k * 128 + j0);
        ulonglong2 b23 = *reinterpret_cast<const ulonglong2*>(Bs + k * 128 + j0 + 4);
#pragma unroll
        for (int i = 0; i < 8; ++i) {
            float a = As[(r0 + i) * 128 + k];
            ull a2 = pk2(a, a);
            ffma2(acc2[i][0], a2, b01.x);
            ffma2(acc2[i][1], a2, b01.y);
            ffma2(acc2[i][2], a2, b23.x);
            ffma2(acc2[i][3], a2, b23.y);
        }
    }
}

__device__ __forceinline__ void zero_acc(ull (&acc2)[8][4]) {
#pragma unroll
    for (int i = 0; i < 8; ++i)
#pragma unroll
        for (int p = 0; p < 4; ++p) acc2[i][p] = 0ULL;
}

// LayerNorm rows held in registers (8x8 block per thread, 16 threads per 8-row
// group = one half-warp) -> normalized result written to smem hs.
__device__ __forceinline__ void ln_store(const float (&xr)[8][8], float* __restrict__ hs,
                                         const float* __restrict__ g,
                                         const float* __restrict__ b,
                                         int r0, int j0) {
    float4 gg0 = *reinterpret_cast<const float4*>(g + j0);
    float4 gg1 = *reinterpret_cast<const float4*>(g + j0 + 4);
    float4 bb0 = *reinterpret_cast<const float4*>(b + j0);
    float4 bb1 = *reinterpret_cast<const float4*>(b + j0 + 4);
    float gv[8] = {gg0.x, gg0.y, gg0.z, gg0.w, gg1.x, gg1.y, gg1.z, gg1.w};
    float bv[8] = {bb0.x, bb0.y, bb0.z, bb0.w, bb1.x, bb1.y, bb1.z, bb1.w};
#pragma unroll
    for (int i = 0; i < 8; ++i) {
        float s = 0.f;
#pragma unroll
        for (int j = 0; j < 8; ++j) s += xr[i][j];
        s = red16(s);
        float m = s * (1.0f / 128.0f);
        float q = 0.f;
#pragma unroll
        for (int j = 0; j < 8; ++j) { float d = xr[i][j] - m; q += d * d; }
        q = red16(q);
        float rs = rsqrtf(q * (1.0f / 128.0f) + EPSm);
        float h[8];
#pragma unroll
        for (int j = 0; j < 8; ++j) h[j] = (xr[i][j] - m) * rs * gv[j] + bv[j];
        float4* d4 = reinterpret_cast<float4*>(hs + (r0 + i) * 128 + j0);
        d4[0] = make_float4(h[0], h[1], h[2], h[3]);
        d4[1] = make_float4(h[4], h[5], h[6], h[7]);
    }
}

// ============================ kernels ============================

// Gram partials: per grid-stride 128-row tile, h = LN1(x); P += h^T h.
__global__ void __launch_bounds__(256, 1)
kg_kernel(const float* __restrict__ xin, const float* __restrict__ lng,
          const float* __restrict__ lnb, int srcIsG) {
    extern __shared__ float hs[];  // 128 x 128
    const float* src = srcIsG ? g_x : xin;
    int tid = threadIdx.x;
    int lane = tid & 31, warp = tid >> 5;
    int ti = tid & 15, tw = tid >> 4;
    int i0 = tw * 8, j0 = ti * 8;
    float4 gv = reinterpret_cast<const float4*>(lng)[lane];
    float4 bv = reinterpret_cast<const float4*>(lnb)[lane];
    ull acc2[8][4];
    zero_acc(acc2);

    for (int t = blockIdx.x; t < NTILESm; t += NPARTm) {
        const float* xt = src + (size_t)t * 128 * 128;
#pragma unroll 2
        for (int rr = 0; rr < 16; ++rr) {
            int r = warp * 16 + rr;
            float4 v = reinterpret_cast<const float4*>(xt + r * 128)[lane];
            float s = v.x + v.y + v.z + v.w;
            s = red32(s);
            float m = s * (1.0f / 128.0f);
            float dx = v.x - m, dy = v.y - m, dz = v.z - m, dw = v.w - m;
            float q = dx * dx + dy * dy + dz * dz + dw * dw;
            q = red32(q);
            float rs = rsqrtf(q * (1.0f / 128.0f) + EPSm);
            float4 h;
            h.x = dx * rs * gv.x + bv.x;
            h.y = dy * rs * gv.y + bv.y;
            h.z = dz * rs * gv.z + bv.z;
            h.w = dw * rs * gv.w + bv.w;
            reinterpret_cast<float4*>(hs + r * 128)[lane] = h;
        }
        __syncthreads();
#pragma unroll 2
        for (int r = 0; r < 128; ++r) {
            ulonglong2 b01 = *reinterpret_cast<const ulonglong2*>(hs + r * 128 + j0);
            ulonglong2 b23 = *reinterpret_cast<const ulonglong2*>(hs + r * 128 + j0 + 4);
            float4 a03 = *reinterpret_cast<const float4*>(hs + r * 128 + i0);
            float4 a47 = *reinterpret_cast<const float4*>(hs + r * 128 + i0 + 4);
            float av[8] = {a03.x, a03.y, a03.z, a03.w, a47.x, a47.y, a47.z, a47.w};
#pragma unroll
            for (int i = 0; i < 8; ++i) {
                ull a2 = pk2(av[i], av[i]);
                ffma2(acc2[i][0], a2, b01.x);
                ffma2(acc2[i][1], a2, b01.y);
                ffma2(acc2[i][2], a2, b23.x);
                ffma2(acc2[i][3], a2, b23.y);
            }
        }
        __syncthreads();
    }
    float* dst = g_part + (size_t)blockIdx.x * Dm * Dm;
#pragma unroll
    for (int i = 0; i < 8; ++i) {
        float o[8];
#pragma unroll
        for (int p = 0; p < 4; ++p) upk2(acc2[i][p], o[2 * p], o[2 * p + 1]);
        float4* d4 = reinterpret_cast<float4*>(dst + (i0 + i) * 128 + j0);
        d4[0] = make_float4(o[0], o[1], o[2], o[3]);
        d4[1] = make_float4(o[4], o[5], o[6], o[7]);
    }
}

// Reduce partials -> G
__global__ void kred_kernel() {
    int idx = blockIdx.x * 256 + threadIdx.x;
    float s = 0.f;
#pragma unroll 8
    for (int p = 0; p < NPARTm; ++p) s += g_part[(size_t)p * (Dm * Dm) + idx];
    g_G[idx] = s;
}

// Tiny 128x128x128 GEMM chain: op0: T1 = G @ Vw; op1: T2 = Kw^T @ T1; op2: M = Qw @ T2
__global__ void __launch_bounds__(256, 1)
ktiny_kernel(const float* __restrict__ Aext, const float* __restrict__ Bext, int op) {
    extern __shared__ float Bs[];  // 64 KB
    const float* A = (op == 0) ? g_G : Aext;
    const float* B = (op == 0) ? Bext : ((op == 1) ? g_T1 : g_T2);
    float* C = (op == 0) ? g_T1 : ((op == 1) ? g_T2 : g_M);
    int tid = threadIdx.x;
    for (int idx = tid; idx < 4096; idx += 256)
        reinterpret_cast<float4*>(Bs)[idx] = reinterpret_cast<const float4*>(B)[idx];
    __syncthreads();
    int warp = tid >> 5, lane = tid & 31;
    int r = blockIdx.x * 8 + warp;
    float4 c = make_float4(0.f, 0.f, 0.f, 0.f);
    if (op == 1) {
#pragma unroll 8
        for (int k = 0; k < 128; ++k) {
            float a = A[k * 128 + r];
            float4 b = reinterpret_cast<const float4*>(Bs + k * 128)[lane];
            c.x += a * b.x; c.y += a * b.y; c.z += a * b.z; c.w += a * b.w;
        }
    } else {
#pragma unroll 8
        for (int k = 0; k < 128; ++k) {
            float a = A[r * 128 + k];
            float4 b = reinterpret_cast<const float4*>(Bs + k * 128)[lane];
            c.x += a * b.x; c.y += a * b.y; c.z += a * b.z; c.w += a * b.w;
        }
    }
    reinterpret_cast<float4*>(C + r * 128)[lane] = c;
}

// The big fused kernel: per 128-row tile:
//   h = LN1(x); x += h @ M; h2 = LN2(x);
//   for 4 chunks: f = relu(h2 @ w1_c + b1_c); x += f @ w2_c;  x += b2
//   last step: out = x @ out_w + out_b  (else store x)
__global__ void __launch_bounds__(256, 1)
kc_kernel(const float* __restrict__ xin, int srcIsG,
          const float* __restrict__ ln1g, const float* __restrict__ ln1b,
          const float* __restrict__ ln2g, const float* __restrict__ ln2b,
          const float* __restrict__ w1, const float* __restrict__ b1,
          const float* __restrict__ w2, const float* __restrict__ b2,
          const float* __restrict__ outw, const float* __restrict__ outb,
          float* __restrict__ outp, int last) {
    extern __shared__ float smdyn[];
    float* hs = smdyn;            // h / h2 / (last) x_new
    float* ws = smdyn + 16384;    // current weight tile
    float* fs = smdyn + 32768;    // relu chunk
    const float* src = srcIsG ? g_x : xin;
    int tid = threadIdx.x;
    int ti = tid & 15, tw = tid >> 4;
    int r0 = tw * 8, j0 = ti * 8;
    size_t base = (size_t)blockIdx.x * 128 * 128;

    float xr[8][8];
#pragma unroll
    for (int i = 0; i < 8; ++i) {
        const float4* p = reinterpret_cast<const float4*>(src + base + (r0 + i) * 128 + j0);
        float4 v0 = p[0], v1 = p[1];
        xr[i][0] = v0.x; xr[i][1] = v0.y; xr[i][2] = v0.z; xr[i][3] = v0.w;
        xr[i][4] = v1.x; xr[i][5] = v1.y; xr[i][6] = v1.z; xr[i][7] = v1.w;
    }

    // LN1 -> hs ; load M -> ws
    ln_store(xr, hs, ln1g, ln1b, r0, j0);
    for (int idx = tid; idx < 4096; idx += 256)
        reinterpret_cast<float4*>(ws)[idx] = reinterpret_cast<const float4*>(g_M)[idx];
    __syncthreads();

    {
        ull acc2[8][4];
        zero_acc(acc2);
        mm88(hs, ws, r0, j0, acc2);
#pragma unroll
        for (int i = 0; i < 8; ++i)
#pragma unroll
            for (int p = 0; p < 4; ++p) {
                float lo, hi; upk2(acc2[i][p], lo, hi);
                xr[i][2 * p] += lo; xr[i][2 * p + 1] += hi;
            }
    }
    __syncthreads();          // everyone done reading hs/ws

    // LN2 -> hs
    ln_store(xr, hs, ln2g, ln2b, r0, j0);

    // FF sublayer, 4 chunks of 128 over the 512-wide hidden dim
#pragma unroll 1
    for (int c = 0; c < 4; ++c) {
        __syncthreads();      // ws free (and hs ready on c==0)
        for (int idx = tid; idx < 4096; idx += 256) {
            int k = idx >> 5, q = idx & 31;
            reinterpret_cast<float4*>(ws)[idx] =
                reinterpret_cast<const float4*>(w1)[k * 128 + c * 32 + q];
        }
        __syncthreads();
        ull acc2[8][4];
        zero_acc(acc2);
        mm88(hs, ws, r0, j0, acc2);   // f_pre = h2 @ w1_c
        // bias + relu -> fs
        {
            float4 bb0 = *reinterpret_cast<const float4*>(b1 + c * 128 + j0);
            float4 bb1 = *reinterpret_cast<const float4*>(b1 + c * 128 + j0 + 4);
            float bv[8] = {bb0.x, bb0.y, bb0.z, bb0.w, bb1.x, bb1.y, bb1.z, bb1.w};
#pragma unroll
            for (int i = 0; i < 8; ++i) {
                float f[8];
#pragma unroll
                for (int p = 0; p < 4; ++p) upk2(acc2[i][p], f[2 * p], f[2 * p + 1]);
#pragma unroll
                for (int j = 0; j < 8; ++j) f[j] = fmaxf(f[j] + bv[j], 0.f);
                float4* d4 = reinterpret_cast<float4*>(fs + (r0 + i) * 128 + j0);
                d4[0] = make_float4(f[0], f[1], f[2], f[3]);
                d4[1] = make_float4(f[4], f[5], f[6], f[7]);
            }
        }
        __syncthreads();      // ws free, fs visible
        for (int idx = tid; idx < 4096; idx += 256)
            reinterpret_cast<float4*>(ws)[idx] =
                reinterpret_cast<const float4*>(w2)[c * 4096 + idx];
        __syncthreads();
        ull acc2b[8][4];
        zero_acc(acc2b);
        mm88(fs, ws, r0, j0, acc2b);  // x += f @ w2_c
#pragma unroll
        for (int i = 0; i < 8; ++i)
#pragma unroll
            for (int p = 0; p < 4; ++p) {
                float lo, hi; upk2(acc2b[i][p], lo, hi);
                xr[i][2 * p] += lo; xr[i][2 * p + 1] += hi;
            }
    }

    // + b2
    {
        float4 bb0 = *reinterpret_cast<const float4*>(b2 + j0);
        float4 bb1 = *reinterpret_cast<const float4*>(b2 + j0 + 4);
        float bv[8] = {bb0.x, bb0.y, bb0.z, bb0.w, bb1.x, bb1.y, bb1.z, bb1.w};
#pragma unroll
        for (int i = 0; i < 8; ++i)
#pragma unroll
            for (int j = 0; j < 8; ++j) xr[i][j] += bv[j];
    }

    if (!last) {
#pragma unroll
        for (int i = 0; i < 8; ++i) {
            float4* d4 = reinterpret_cast<float4*>(g_x + base + (r0 + i) * 128 + j0);
            d4[0] = make_float4(xr[i][0], xr[i][1], xr[i][2], xr[i][3]);
            d4[1] = make_float4(xr[i][4], xr[i][5], xr[i][6], xr[i][7]);
        }
    } else {
        // out = x_new @ out_w + out_b, fused
        __syncthreads();      // laggards may still read fs/ws; hs reads all done
#pragma unroll
        for (int i = 0; i < 8; ++i) {
            float4* d4 = reinterpret_cast<float4*>(hs + (r0 + i) * 128 + j0);
            d4[0] = make_float4(xr[i][0], xr[i][1], xr[i][2], xr[i][3]);
            d4[1] = make_float4(xr[i][4], xr[i][5], xr[i][6], xr[i][7]);
        }
        __syncthreads();      // x_new in hs visible; ws still being read? no: sync above
        for (int idx = tid; idx < 4096; idx += 256)
            reinterpret_cast<float4*>(ws)[idx] = reinterpret_cast<const float4*>(outw)[idx];
        __syncthreads();
        ull acc2[8][4];
        zero_acc(acc2);
        mm88(hs, ws, r0, j0, acc2);
        float4 bb0 = *reinterpret_cast<const float4*>(outb + j0);
        float4 bb1 = *reinterpret_cast<const float4*>(outb + j0 + 4);
        float bv[8] = {bb0.x, bb0.y, bb0.z, bb0.w, bb1.x, bb1.y, bb1.z, bb1.w};
#pragma unroll
        for (int i = 0; i < 8; ++i) {
            float o[8];
#pragma unroll
            for (int p = 0; p < 4; ++p) upk2(acc2[i][p], o[2 * p], o[2 * p + 1]);
#pragma unroll
            for (int j = 0; j < 8; ++j) o[j] += bv[j];
            float4* d4 = reinterpret_cast<float4*>(outp + base + (r0 + i) * 128 + j0);
            d4[0] = make_float4(o[0], o[1], o[2], o[3]);
            d4[1] = make_float4(o[4], o[5], o[6], o[7]);
        }
    }
}

// ============================ host launcher ============================
extern "C" void kernel_launch(void* const* d_in, const int* in_sizes, int n_in,
                              void* d_out, int out_size) {
    (void)in_sizes; (void)n_in; (void)out_size;
    const float* x    = (const float*)d_in[0];
    const float* Kw   = (const float*)d_in[1];
    const float* Qw   = (const float*)d_in[2];
    const float* Vw   = (const float*)d_in[3];
    const float* ln1g = (const float*)d_in[4];
    const float* ln1b = (const float*)d_in[5];
    const float* ln2g = (const float*)d_in[6];
    const float* ln2b = (const float*)d_in[7];
    const float* w1   = (const float*)d_in[8];
    const float* b1   = (const float*)d_in[9];
    const float* w2   = (const float*)d_in[10];
    const float* b2   = (const float*)d_in[11];
    const float* outw = (const float*)d_in[12];
    const float* outb = (const float*)d_in[13];
    float* out = (float*)d_out;

    cudaFuncSetAttribute(kc_kernel, cudaFuncAttributeMaxDynamicSharedMemorySize, 196608);
    cudaFuncSetAttribute(kg_kernel, cudaFuncAttributeMaxDynamicSharedMemorySize, 65536);
    cudaFuncSetAttribute(ktiny_kernel, cudaFuncAttributeMaxDynamicSharedMemorySize, 65536);

    for (int t = 0; t < 4; ++t) {
        int srcIsG = (t != 0);
        kg_kernel<<<NPARTm, 256, 65536>>>(x, ln1g, ln1b, srcIsG);
        kred_kernel<<<64, 256>>>();
        ktiny_kernel<<<16, 256, 65536>>>(nullptr, Vw, 0);  // T1 = G @ Vw
        ktiny_kernel<<<16, 256, 65536>>>(Kw, nullptr, 1);  // T2 = Kw^T @ T1
        ktiny_kernel<<<16, 256, 65536>>>(Qw, nullptr, 2);  // M  = Qw @ T2
        kc_kernel<<<NTILESm, 256, 196608>>>(x, srcIsG, ln1g, ln1b, ln2g, ln2b,
                                            w1, b1, w2, b2, outw, outb, out, t == 3);
    }
}

// round 4
// speedup vs baseline: 2.3815x; 2.3815x over previous
#include <cuda_runtime.h>
#include <cuda_bf16.h>
#include <cstdint>

#define EPSm   1e-5f
#define NROWSm 131072
#define NTILESm 1024
#define NPARTm 296

// ---------------- device scratch ----------------
__device__ float g_x[NROWSm * 128];
__device__ float g_part[NPARTm * 128 * 128];
__device__ float g_QK[128 * 128];
__device__ float g_T1[128 * 128];
__device__ __nv_bfloat16 g_Mt_hi[128 * 128],  g_Mt_lo[128 * 128];
__device__ __nv_bfloat16 g_w1t_hi[512 * 128], g_w1t_lo[512 * 128];
__device__ __nv_bfloat16 g_w2t_hi[128 * 512], g_w2t_lo[128 * 512];
__device__ __nv_bfloat16 g_owt_hi[128 * 128], g_owt_lo[128 * 128];

// ---------------- helpers ----------------
__device__ __forceinline__ uint32_t smem_u32(const void* p) {
    uint32_t a;
    asm("{ .reg .u64 t; cvta.to.shared.u64 t, %1; cvt.u32.u64 %0, t; }" : "=r"(a) : "l"(p));
    return a;
}
// XOR-swizzled tile: 128 rows x 256B (128 bf16).
__device__ __forceinline__ uint32_t sw16(int r, int c8) {
    return (uint32_t)(r * 256 + ((c8 ^ (r & 7)) << 4));
}
__device__ __forceinline__ uint32_t sw4(int r, int col) {
    return (uint32_t)(r * 256 + ((((col >> 3) ^ (r & 7)) << 4)) + (col & 7) * 2);
}
__device__ __forceinline__ void split2(float f0, float f1, uint32_t& hi, uint32_t& lo) {
    __nv_bfloat162 H = __floats2bfloat162_rn(f0, f1);
    float r0 = f0 - __bfloat162float(H.x);
    float r1 = f1 - __bfloat162float(H.y);
    __nv_bfloat162 L = __floats2bfloat162_rn(r0, r1);
    hi = *reinterpret_cast<uint32_t*>(&H);
    lo = *reinterpret_cast<uint32_t*>(&L);
}
__device__ __forceinline__ void sp1(float v, __nv_bfloat16* h, __nv_bfloat16* l) {
    __nv_bfloat16 hh = __float2bfloat16(v);
    *h = hh;
    *l = __float2bfloat16(v - __bfloat162float(hh));
}
__device__ __forceinline__ void ldsm4(uint32_t* r, uint32_t a) {
    asm volatile("ldmatrix.sync.aligned.m8n8.x4.shared.b16 {%0,%1,%2,%3}, [%4];"
                 : "=r"(r[0]), "=r"(r[1]), "=r"(r[2]), "=r"(r[3]) : "r"(a));
}
__device__ __forceinline__ void ldsm2(uint32_t* r, uint32_t a) {
    asm volatile("ldmatrix.sync.aligned.m8n8.x2.shared.b16 {%0,%1}, [%2];"
                 : "=r"(r[0]), "=r"(r[1]) : "r"(a));
}
__device__ __forceinline__ void ldsm4t(uint32_t* r, uint32_t a) {
    asm volatile("ldmatrix.sync.aligned.m8n8.x4.trans.shared.b16 {%0,%1,%2,%3}, [%4];"
                 : "=r"(r[0]), "=r"(r[1]), "=r"(r[2]), "=r"(r[3]) : "r"(a));
}
__device__ __forceinline__ void ldsm2t(uint32_t* r, uint32_t a) {
    asm volatile("ldmatrix.sync.aligned.m8n8.x2.trans.shared.b16 {%0,%1}, [%2];"
                 : "=r"(r[0]), "=r"(r[1]) : "r"(a));
}
__device__ __forceinline__ void mma_bf16(float* c, const uint32_t* a, const uint32_t* b) {
    asm volatile(
        "mma.sync.aligned.m16n8k16.row.col.f32.bf16.bf16.f32 "
        "{%0,%1,%2,%3}, {%4,%5,%6,%7}, {%8,%9}, {%0,%1,%2,%3};"
        : "+f"(c[0]), "+f"(c[1]), "+f"(c[2]), "+f"(c[3])
        : "r"(a[0]), "r"(a[1]), "r"(a[2]), "r"(a[3]), "r"(b[0]), "r"(b[1]));
}

// C[128][128] += A[128][128] @ Bt[128][128]^T, bf16 3-split.
// A row-major [m][k], Bt row-major [n][k]; both swizzled smem tiles.
__device__ __forceinline__ void mma_nt(float (&acc)[4][4][4],
                                       uint32_t aHi, uint32_t aLo,
                                       uint32_t bHi, uint32_t bLo,
                                       int warp_m, int warp_n, int lane) {
#pragma unroll
    for (int k8 = 0; k8 < 8; ++k8) {
        uint32_t aH[4][4], aL[4][4], bH[4][2], bL[4][2];
        int ar = warp_m * 64 + (lane & 15);
        int ac8 = k8 * 2 + (lane >> 4);
#pragma unroll
        for (int mi = 0; mi < 4; ++mi) {
            uint32_t off = sw16(ar + mi * 16, ac8);
            ldsm4(aH[mi], aHi + off);
            ldsm4(aL[mi], aLo + off);
        }
        int l15 = lane & 15;
        int br = warp_n * 32 + (l15 & 7);
        int bc8 = k8 * 2 + (l15 >> 3);
#pragma unroll
        for (int ni = 0; ni < 4; ++ni) {
            uint32_t off = sw16(br + ni * 8, bc8);
            ldsm2(bH[ni], bHi + off);
            ldsm2(bL[ni], bLo + off);
        }
#pragma unroll
        for (int mi = 0; mi < 4; ++mi)
#pragma unroll
            for (int ni = 0; ni < 4; ++ni) {
                mma_bf16(acc[mi][ni], aH[mi], bH[ni]);
                mma_bf16(acc[mi][ni], aH[mi], bL[ni]);
                mma_bf16(acc[mi][ni], aL[mi], bH[ni]);
            }
    }
}

// Gram: C += H^T @ H, bf16 3-split; H row-major [r][i], trans loads.
__device__ __forceinline__ void mma_tt(float (&acc)[4][4][4],
                                       uint32_t hHi, uint32_t hLo,
                                       int warp_m, int warp_n, int lane) {
#pragma unroll
    for (int k8 = 0; k8 < 8; ++k8) {
        int k0 = k8 * 16;
        uint32_t aH[4][4], aL[4][4], bH[4][2], bL[4][2];
        int ar = k0 + (lane & 7) + ((lane >> 4) << 3);
        int asel = (lane >> 3) & 1;
#pragma unroll
        for (int mi = 0; mi < 4; ++mi) {
            int c8 = ((warp_m * 64 + mi * 16) >> 3) + asel;
            uint32_t off = sw16(ar, c8);
            ldsm4t(aH[mi], hHi + off);
            ldsm4t(aL[mi], hLo + off);
        }
        int l15 = lane & 15;
        int br = k0 + (l15 & 7) + ((l15 >> 3) << 3);
#pragma unroll
        for (int ni = 0; ni < 4; ++ni) {
            int c8 = (warp_n * 32 + ni * 8) >> 3;
            uint32_t off = sw16(br, c8);
            ldsm2t(bH[ni], hHi + off);
            ldsm2t(bL[ni], hLo + off);
        }
#pragma unroll
        for (int mi = 0; mi < 4; ++mi)
#pragma unroll
            for (int ni = 0; ni < 4; ++ni) {
                mma_bf16(acc[mi][ni], aH[mi], bH[ni]);
                mma_bf16(acc[mi][ni], aH[mi], bL[ni]);
                mma_bf16(acc[mi][ni], aL[mi], bH[ni]);
            }
    }
}

// LayerNorm of fragment-layout values -> split hi/lo into swizzled tile.
__device__ __forceinline__ void ln_acc(const float (&v)[4][4][4],
                                       const float* gs, const float* bs,
                                       char* Ahi, char* Alo,
                                       float2* red, float2* mrs,
                                       int warp_m, int warp_n, int lane, int tid) {
    int row0 = warp_m * 64 + (lane >> 2);
    int col0 = warp_n * 32 + (lane & 3) * 2;
#pragma unroll
    for (int mi = 0; mi < 4; ++mi) {
        float s1 = 0, q1 = 0, s2 = 0, q2 = 0;
#pragma unroll
        for (int ni = 0; ni < 4; ++ni) {
            s1 += v[mi][ni][0] + v[mi][ni][1];
            q1 += v[mi][ni][0] * v[mi][ni][0] + v[mi][ni][1] * v[mi][ni][1];
            s2 += v[mi][ni][2] + v[mi][ni][3];
            q2 += v[mi][ni][2] * v[mi][ni][2] + v[mi][ni][3] * v[mi][ni][3];
        }
        s1 += __shfl_xor_sync(~0u, s1, 1); s1 += __shfl_xor_sync(~0u, s1, 2);
        q1 += __shfl_xor_sync(~0u, q1, 1); q1 += __shfl_xor_sync(~0u, q1, 2);
        s2 += __shfl_xor_sync(~0u, s2, 1); s2 += __shfl_xor_sync(~0u, s2, 2);
        q2 += __shfl_xor_sync(~0u, q2, 1); q2 += __shfl_xor_sync(~0u, q2, 2);
        if ((lane & 3) == 0) {
            int r1 = row0 + mi * 16;
            red[r1 * 4 + warp_n] = make_float2(s1, q1);
            red[(r1 + 8) * 4 + warp_n] = make_float2(s2, q2);
        }
    }
    __syncthreads();
    if (tid < 128) {
        float s = 0, q = 0;
#pragma unroll
        for (int w = 0; w < 4; ++w) { float2 p = red[tid * 4 + w]; s += p.x; q += p.y; }
        float m = s * (1.0f / 128.0f);
        float var = q * (1.0f / 128.0f) - m * m;
        mrs[tid] = make_float2(m, rsqrtf(var + EPSm));
    }
    __syncthreads();
#pragma unroll
    for (int mi = 0; mi < 4; ++mi) {
        float2 m1 = mrs[row0 + mi * 16];
        float2 m2 = mrs[row0 + mi * 16 + 8];
#pragma unroll
        for (int ni = 0; ni < 4; ++ni) {
            int col = col0 + ni * 8;
            float g0 = gs[col], g1 = gs[col + 1], bb0 = bs[col], bb1 = bs[col + 1];
            int r1 = row0 + mi * 16, r2 = r1 + 8;
            float f0 = (v[mi][ni][0] - m1.x) * m1.y * g0 + bb0;
            float f1 = (v[mi][ni][1] - m1.x) * m1.y * g1 + bb1;
            float f2 = (v[mi][ni][2] - m2.x) * m2.y * g0 + bb0;
            float f3 = (v[mi][ni][3] - m2.x) * m2.y * g1 + bb1;
            uint32_t h, l;
            uint32_t o1 = sw4(r1, col), o2 = sw4(r2, col);
            split2(f0, f1, h, l);
            *reinterpret_cast<uint32_t*>(Ahi + o1) = h;
            *reinterpret_cast<uint32_t*>(Alo + o1) = l;
            split2(f2, f3, h, l);
            *reinterpret_cast<uint32_t*>(Ahi + o2) = h;
            *reinterpret_cast<uint32_t*>(Alo + o2) = l;
        }
    }
    __syncthreads();
}

// copy 128x128 bf16 tile (global row-major, rs_u4 uint4s/row) -> swizzled smem (256 thr)
__device__ __forceinline__ void copy_tile(char* dst, const uint4* __restrict__ src,
                                          int rs_u4, int tid) {
#pragma unroll
    for (int i = 0; i < 8; ++i) {
        int idx = tid + i * 256;
        int r = idx >> 4, c8 = idx & 15;
        *reinterpret_cast<uint4*>(dst + sw16(r, c8)) = src[r * rs_u4 + c8];
    }
}

// ============================ kernels ============================

__global__ void kprep_kernel(const float* __restrict__ w1, const float* __restrict__ w2,
                             const float* __restrict__ outw) {
    int idx = blockIdx.x * 256 + threadIdx.x;
    if (idx < 65536) {                 // w1t [512 n][128 k]
        int n = idx >> 7, k = idx & 127;
        sp1(w1[k * 512 + n], &g_w1t_hi[idx], &g_w1t_lo[idx]);
    } else if (idx < 131072) {         // w2t [128 n][512 k]
        int j = idx - 65536;
        int n = j >> 9, k = j & 511;
        sp1(w2[k * 128 + n], &g_w2t_hi[j], &g_w2t_lo[j]);
    } else if (idx < 147456) {         // owt [128 n][128 k]
        int j = idx - 131072;
        int n = j >> 7, k = j & 127;
        sp1(outw[k * 128 + n], &g_owt_hi[j], &g_owt_lo[j]);
    }
}

// Gram partials via HMMA: per tile h = LN1(x); P += h^T h.
#define KG_SMEM (6144 + 65536)
__global__ void __launch_bounds__(256, 1)
kg_mma(const float* __restrict__ xin, int srcIsG,
       const float* __restrict__ lng, const float* __restrict__ lnb) {
    extern __shared__ char sm[];
    float* gs = reinterpret_cast<float*>(sm);
    float* bs = gs + 128;
    float2* red = reinterpret_cast<float2*>(sm + 1024);
    float2* mrs = reinterpret_cast<float2*>(sm + 5120);
    char* Hhi = sm + 6144;
    char* Hlo = sm + 6144 + 32768;
    uint32_t smb = smem_u32(sm);
    uint32_t hHi = smb + 6144, hLo = smb + 6144 + 32768;
    int tid = threadIdx.x, lane = tid & 31, wid = tid >> 5;
    int warp_m = wid & 1, warp_n = wid >> 1;
    int row0 = warp_m * 64 + (lane >> 2);
    int col0 = warp_n * 32 + (lane & 3) * 2;
    if (tid < 128) { gs[tid] = lng[tid]; bs[tid] = lnb[tid]; }
    __syncthreads();
    const float* src = srcIsG ? g_x : xin;

    float acc[4][4][4];
#pragma unroll
    for (int mi = 0; mi < 4; ++mi)
#pragma unroll
        for (int ni = 0; ni < 4; ++ni)
#pragma unroll
            for (int e = 0; e < 4; ++e) acc[mi][ni][e] = 0.f;

    for (int t = blockIdx.x; t < NTILESm; t += NPARTm) {
        const float* xt = src + (size_t)t * 16384;
        float v[4][4][4];
#pragma unroll
        for (int mi = 0; mi < 4; ++mi)
#pragma unroll
            for (int ni = 0; ni < 4; ++ni) {
                const float* p = xt + (row0 + mi * 16) * 128 + col0 + ni * 8;
                float2 a = *reinterpret_cast<const float2*>(p);
                float2 b = *reinterpret_cast<const float2*>(p + 8 * 128);
                v[mi][ni][0] = a.x; v[mi][ni][1] = a.y;
                v[mi][ni][2] = b.x; v[mi][ni][3] = b.y;
            }
        ln_acc(v, gs, bs, Hhi, Hlo, red, mrs, warp_m, warp_n, lane, tid);
        mma_tt(acc, hHi, hLo, warp_m, warp_n, lane);
        __syncthreads();
    }
    float* dst = g_part + (size_t)blockIdx.x * 16384;
#pragma unroll
    for (int mi = 0; mi < 4; ++mi)
#pragma unroll
        for (int ni = 0; ni < 4; ++ni) {
            int r1 = row0 + mi * 16, col = col0 + ni * 8;
            *reinterpret_cast<float2*>(dst + r1 * 128 + col) =
                make_float2(acc[mi][ni][0], acc[mi][ni][1]);
            *reinterpret_cast<float2*>(dst + (r1 + 8) * 128 + col) =
                make_float2(acc[mi][ni][2], acc[mi][ni][3]);
        }
}

// Small GEMMs. op0: g_QK = A(Qw) @ B(Kw)^T. op1: g_T1 = (sum g_part) @ B(Vw).
// op2: Mt(bf16 split) = g_QK @ g_T1.
#define TS_SMEM (128 * 129 * 4 + 512 * 4)
__global__ void __launch_bounds__(256, 1)
ktiny2(const float* __restrict__ A, const float* __restrict__ B, int op) {
    extern __shared__ float ts[];
    float* Bs = ts;              // [128][129]
    float* As = ts + 128 * 129;  // [4][128]
    int tid = threadIdx.x;
    const float* Bp = (op == 2) ? g_T1 : B;
    for (int idx = tid; idx < 16384; idx += 256)
        Bs[(idx >> 7) * 129 + (idx & 127)] = Bp[idx];
    int r0 = blockIdx.x * 4;
    if (op == 1) {
        for (int idx = tid; idx < 512; idx += 256) {
            int i = idx >> 7, k = idx & 127;
            float s = 0.f;
#pragma unroll 4
            for (int p = 0; p < NPARTm; ++p)
                s += g_part[(size_t)p * 16384 + (r0 + i) * 128 + k];
            As[idx] = s;
        }
    } else {
        const float* Ap = (op == 2) ? g_QK : A;
        for (int idx = tid; idx < 512; idx += 256)
            As[idx] = Ap[(r0 + (idx >> 7)) * 128 + (idx & 127)];
    }
    __syncthreads();
    int j = tid & 127, i0 = (tid >> 7) * 2;
    float c0 = 0.f, c1 = 0.f;
    if (op == 0) {
#pragma unroll 8
        for (int k = 0; k < 128; ++k) {
            float b = Bs[j * 129 + k];
            c0 = fmaf(As[i0 * 128 + k], b, c0);
            c1 = fmaf(As[i0 * 128 + 128 + k], b, c1);
        }
    } else {
#pragma unroll 8
        for (int k = 0; k < 128; ++k) {
            float b = Bs[k * 129 + j];
            c0 = fmaf(As[i0 * 128 + k], b, c0);
            c1 = fmaf(As[i0 * 128 + 128 + k], b, c1);
        }
    }
    if (op == 2) {
        sp1(c0, &g_Mt_hi[j * 128 + r0 + i0], &g_Mt_lo[j * 128 + r0 + i0]);
        sp1(c1, &g_Mt_hi[j * 128 + r0 + i0 + 1], &g_Mt_lo[j * 128 + r0 + i0 + 1]);
    } else {
        float* C = (op == 0) ? g_QK : g_T1;
        C[(r0 + i0) * 128 + j] = c0;
        C[(r0 + i0 + 1) * 128 + j] = c1;
    }
}

// ================= big fused kernel (HMMA) =================
#define KC_RED  5120
#define KC_MRS  9216
#define KC_AHI  10240
#define KC_ALO  (KC_AHI + 32768)
#define KC_BHI  (KC_AHI + 65536)
#define KC_BLO  (KC_AHI + 98304)
#define KC_FHI  (KC_AHI + 131072)
#define KC_FLO  (KC_AHI + 163840)
#define KC_SMEM (KC_AHI + 196608)   // 206848

__global__ void __launch_bounds__(256, 1)
kc_mma(const float* __restrict__ xin, int srcIsG,
       const float* __restrict__ ln1g, const float* __restrict__ ln1b,
       const float* __restrict__ ln2g, const float* __restrict__ ln2b,
       const float* __restrict__ b1, const float* __restrict__ b2,
       const float* __restrict__ outb, float* __restrict__ outp, int last) {
    extern __shared__ char sm[];
    uint32_t smb = smem_u32(sm);
    int tid = threadIdx.x, lane = tid & 31, wid = tid >> 5;
    int warp_m = wid & 1, warp_n = wid >> 1;
    int row0 = warp_m * 64 + (lane >> 2);
    int col0 = warp_n * 32 + (lane & 3) * 2;

    float* ln1gs = reinterpret_cast<float*>(sm);          // 128
    float* ln1bs = ln1gs + 128;
    float* ln2gs = ln1gs + 256;
    float* ln2bs = ln1gs + 384;
    float* b2s   = ln1gs + 512;
    float* outbs = ln1gs + 640;
    float* b1s   = ln1gs + 768;                           // 512
    float2* red  = reinterpret_cast<float2*>(sm + KC_RED);
    float2* mrs  = reinterpret_cast<float2*>(sm + KC_MRS);
    if (tid < 128) {
        ln1gs[tid] = ln1g[tid]; ln1bs[tid] = ln1b[tid];
        ln2gs[tid] = ln2g[tid]; ln2bs[tid] = ln2b[tid];
        b2s[tid] = b2[tid]; outbs[tid] = outb[tid];
    }
    b1s[tid] = b1[tid]; b1s[tid + 256] = b1[tid + 256];

    // x in fragment layout
    size_t base = (size_t)blockIdx.x * 16384;
    const float* xt = (srcIsG ? g_x : xin) + base;
    float xr[4][4][4];
#pragma unroll
    for (int mi = 0; mi < 4; ++mi)
#pragma unroll
        for (int ni = 0; ni < 4; ++ni) {
            const float* p = xt + (row0 + mi * 16) * 128 + col0 + ni * 8;
            float2 a = *reinterpret_cast<const float2*>(p);
            float2 b = *reinterpret_cast<const float2*>(p + 8 * 128);
            xr[mi][ni][0] = a.x; xr[mi][ni][1] = a.y;
            xr[mi][ni][2] = b.x; xr[mi][ni][3] = b.y;
        }

    // B <- Mt ; A <- LN1(x)
    copy_tile(sm + KC_BHI, reinterpret_cast<const uint4*>(g_Mt_hi), 16, tid);
    copy_tile(sm + KC_BLO, reinterpret_cast<const uint4*>(g_Mt_lo), 16, tid);
    ln_acc(xr, ln1gs, ln1bs, sm + KC_AHI, sm + KC_ALO, red, mrs, warp_m, warp_n, lane, tid);
    // x += h @ M
    mma_nt(xr, smb + KC_AHI, smb + KC_ALO, smb + KC_BHI, smb + KC_BLO, warp_m, warp_n, lane);
    __syncthreads();

    // A <- LN2(x)
    ln_acc(xr, ln2gs, ln2bs, sm + KC_AHI, sm + KC_ALO, red, mrs, warp_m, warp_n, lane, tid);

    // FF: 4 chunks of 128 hidden units
#pragma unroll 1
    for (int c = 0; c < 4; ++c) {
        copy_tile(sm + KC_BHI, reinterpret_cast<const uint4*>(g_w1t_hi) + c * 2048, 16, tid);
        copy_tile(sm + KC_BLO, reinterpret_cast<const uint4*>(g_w1t_lo) + c * 2048, 16, tid);
        __syncthreads();
        float u[4][4][4];
#pragma unroll
        for (int mi = 0; mi < 4; ++mi)
#pragma unroll
            for (int ni = 0; ni < 4; ++ni)
#pragma unroll
                for (int e = 0; e < 4; ++e) u[mi][ni][e] = 0.f;
        mma_nt(u, smb + KC_AHI, smb + KC_ALO, smb + KC_BHI, smb + KC_BLO, warp_m, warp_n, lane);
        // bias + relu + split -> F
#pragma unroll
        for (int mi = 0; mi < 4; ++mi)
#pragma unroll
            for (int ni = 0; ni < 4; ++ni) {
                int col = col0 + ni * 8;
                float bb0 = b1s[c * 128 + col], bb1 = b1s[c * 128 + col + 1];
                int r1 = row0 + mi * 16, r2 = r1 + 8;
                float f0 = fmaxf(u[mi][ni][0] + bb0, 0.f);
                float f1 = fmaxf(u[mi][ni][1] + bb1, 0.f);
                float f2 = fmaxf(u[mi][ni][2] + bb0, 0.f);
                float f3 = fmaxf(u[mi][ni][3] + bb1, 0.f);
                uint32_t h, l;
                uint32_t o1 = sw4(r1, col), o2 = sw4(r2, col);
                split2(f0, f1, h, l);
                *reinterpret_cast<uint32_t*>(sm + KC_FHI + o1) = h;
                *reinterpret_cast<uint32_t*>(sm + KC_FLO + o1) = l;
                split2(f2, f3, h, l);
                *reinterpret_cast<uint32_t*>(sm + KC_FHI + o2) = h;
                *reinterpret_cast<uint32_t*>(sm + KC_FLO + o2) = l;
            }
        __syncthreads();    // F visible; B(w1) reads done
        copy_tile(sm + KC_BHI, reinterpret_cast<const uint4*>(g_w2t_hi) + c * 16, 64, tid);
        copy_tile(sm + KC_BLO, reinterpret_cast<const uint4*>(g_w2t_lo) + c * 16, 64, tid);
        __syncthreads();
        // x += f @ w2_c
        mma_nt(xr, smb + KC_FHI, smb + KC_FLO, smb + KC_BHI, smb + KC_BLO, warp_m, warp_n, lane);
        __syncthreads();    // B, F free for next chunk
    }

    // + b2
#pragma unroll
    for (int mi = 0; mi < 4; ++mi)
#pragma unroll
        for (int ni = 0; ni < 4; ++ni) {
            int col = col0 + ni * 8;
            xr[mi][ni][0] += b2s[col];     xr[mi][ni][1] += b2s[col + 1];
            xr[mi][ni][2] += b2s[col];     xr[mi][ni][3] += b2s[col + 1];
        }

    if (!last) {
        float* dst = g_x + base;
#pragma unroll
        for (int mi = 0; mi < 4; ++mi)
#pragma unroll
            for (int ni = 0; ni < 4; ++ni) {
                int r1 = row0 + mi * 16, col = col0 + ni * 8;
                *reinterpret_cast<float2*>(dst + r1 * 128 + col) =
                    make_float2(xr[mi][ni][0], xr[mi][ni][1]);
                *reinterpret_cast<float2*>(dst + (r1 + 8) * 128 + col) =
                    make_float2(xr[mi][ni][2], xr[mi][ni][3]);
            }
    } else {
        // out = x @ outw + outb
#pragma unroll
        for (int mi = 0; mi < 4; ++mi)
#pragma unroll
            for (int ni = 0; ni < 4; ++ni) {
                int col = col0 + ni * 8;
                int r1 = row0 + mi * 16, r2 = r1 + 8;
                uint32_t h, l;
                uint32_t o1 = sw4(r1, col), o2 = sw4(r2, col);
                split2(xr[mi][ni][0], xr[mi][ni][1], h, l);
                *reinterpret_cast<uint32_t*>(sm + KC_AHI + o1) = h;
                *reinterpret_cast<uint32_t*>(sm + KC_ALO + o1) = l;
                split2(xr[mi][ni][2], xr[mi][ni][3], h, l);
                *reinterpret_cast<uint32_t*>(sm + KC_AHI + o2) = h;
                *reinterpret_cast<uint32_t*>(sm + KC_ALO + o2) = l;
            }
        copy_tile(sm + KC_BHI, reinterpret_cast<const uint4*>(g_owt_hi), 16, tid);
        copy_tile(sm + KC_BLO, reinterpret_cast<const uint4*>(g_owt_lo), 16, tid);
        __syncthreads();
        float o[4][4][4];
#pragma unroll
        for (int mi = 0; mi < 4; ++mi)
#pragma unroll
            for (int ni = 0; ni < 4; ++ni)
#pragma unroll
                for (int e = 0; e < 4; ++e) o[mi][ni][e] = 0.f;
        mma_nt(o, smb + KC_AHI, smb + KC_ALO, smb + KC_BHI, smb + KC_BLO, warp_m, warp_n, lane);
        float* dst = outp + base;
#pragma unroll
        for (int mi = 0; mi < 4; ++mi)
#pragma unroll
            for (int ni = 0; ni < 4; ++ni) {
                int r1 = row0 + mi * 16, col = col0 + ni * 8;
                *reinterpret_cast<float2*>(dst + r1 * 128 + col) =
                    make_float2(o[mi][ni][0] + outbs[col], o[mi][ni][1] + outbs[col + 1]);
                *reinterpret_cast<float2*>(dst + (r1 + 8) * 128 + col) =
                    make_float2(o[mi][ni][2] + outbs[col], o[mi][ni][3] + outbs[col + 1]);
            }
    }
}

// ============================ host launcher ============================
extern "C" void kernel_launch(void* const* d_in, const int* in_sizes, int n_in,
                              void* d_out, int out_size) {
    (void)in_sizes; (void)n_in; (void)out_size;
    const float* x    = (const float*)d_in[0];
    const float* Kw   = (const float*)d_in[1];
    const float* Qw   = (const float*)d_in[2];
    const float* Vw   = (const float*)d_in[3];
    const float* ln1g = (const float*)d_in[4];
    const float* ln1b = (const float*)d_in[5];
    const float* ln2g = (const float*)d_in[6];
    const float* ln2b = (const float*)d_in[7];
    const float* w1   = (const float*)d_in[8];
    const float* b1   = (const float*)d_in[9];
    const float* w2   = (const float*)d_in[10];
    const float* b2   = (const float*)d_in[11];
    const float* outw = (const float*)d_in[12];
    const float* outb = (const float*)d_in[13];
    float* out = (float*)d_out;

    cudaFuncSetAttribute(kc_mma, cudaFuncAttributeMaxDynamicSharedMemorySize, KC_SMEM);
    cudaFuncSetAttribute(kg_mma, cudaFuncAttributeMaxDynamicSharedMemorySize, KG_SMEM);
    cudaFuncSetAttribute(ktiny2, cudaFuncAttributeMaxDynamicSharedMemorySize, TS_SMEM);

    kprep_kernel<<<576, 256>>>(w1, w2, outw);
    ktiny2<<<32, 256, TS_SMEM>>>(Qw, Kw, 0);   // QK = Qw @ Kw^T

    for (int t = 0; t < 4; ++t) {
        int srcIsG = (t != 0);
        kg_mma<<<NPARTm, 256, KG_SMEM>>>(x, srcIsG, ln1g, ln1b);
        ktiny2<<<32, 256, TS_SMEM>>>(nullptr, Vw, 1);   // T1 = G @ Vw
        ktiny2<<<32, 256, TS_SMEM>>>(nullptr, nullptr, 2); // Mt = QK @ T1 (bf16 split)
        kc_mma<<<NTILESm, 256, KC_SMEM>>>(x, srcIsG, ln1g, ln1b, ln2g, ln2b,
                                          b1, b2, outb, out, t == 3);
    }
}